// round 10
// baseline (speedup 1.0000x reference)
#include <cuda_runtime.h>
#include <cuda_bf16.h>
#include <cstdint>

// ===========================================================================
// Problem constants
// ===========================================================================
#define B_      128
#define RES_    25
#define D_      512
#define C_      64
#define N_      20
#define Q_      (B_ * RES_)      // 3200
#define M_ROWS  (C_ * N_)        // 1280
#define LAM     (20.0f / 512.0f)

// ===========================================================================
// Device scratch (allocation-free)
// ===========================================================================
__device__ float g_V[B_ * C_];                     // 128 x 64 quadform sums
__device__ __nv_bfloat16 g_Ahi[M_ROWS * D_];       // G hi/lo planes (prep)
__device__ __nv_bfloat16 g_Alo[M_ROWS * D_];
__device__ __nv_bfloat16 g_Bhi[Q_ * D_];           // x hi/lo planes (convert)
__device__ __nv_bfloat16 g_Blo[Q_ * D_];

// ===========================================================================
// PTX helpers (base-target only: ldmatrix / mma.sync / cp.async)
// ===========================================================================
__device__ __forceinline__ uint32_t smem_to_u32(const void* p) {
    uint32_t a;
    asm("{ .reg .u64 t; cvta.to.shared.u64 t, %1; cvt.u32.u64 %0, t; }"
        : "=r"(a) : "l"(p));
    return a;
}

#define CP_ASYNC16(dst_u32, src_ptr) \
    asm volatile("cp.async.cg.shared.global [%0], [%1], 16;" \
        :: "r"(dst_u32), "l"(src_ptr) : "memory")
#define CP_COMMIT() asm volatile("cp.async.commit_group;" ::: "memory")
#define CP_WAIT(n)  asm volatile("cp.async.wait_group %0;" :: "n"(n) : "memory")

__device__ __forceinline__ void ldsm_x4(uint32_t r[4], uint32_t addr) {
    asm volatile("ldmatrix.sync.aligned.m8n8.x4.shared.b16 {%0,%1,%2,%3}, [%4];"
        : "=r"(r[0]), "=r"(r[1]), "=r"(r[2]), "=r"(r[3]) : "r"(addr));
}

__device__ __forceinline__ void mma16816(float c[4], const uint32_t a[4],
                                         uint32_t b0, uint32_t b1) {
    asm volatile(
        "mma.sync.aligned.m16n8k16.row.col.f32.bf16.bf16.f32 "
        "{%0,%1,%2,%3},{%4,%5,%6,%7},{%8,%9},{%0,%1,%2,%3};"
        : "+f"(c[0]), "+f"(c[1]), "+f"(c[2]), "+f"(c[3])
        : "r"(a[0]), "r"(a[1]), "r"(a[2]), "r"(a[3]), "r"(b0), "r"(b1));
}

// ===========================================================================
// Kernel 1 (merged): blocks 0..63 run per-class prep; blocks 64.. run the
// x -> bf16 hi/lo convert (float4-vectorized).  Block 64 also zeroes g_V.
//   prep: A = H H^T + lam*I ; M = A^-1 ; S = M + lam*M^2 ; S = L L^T ;
//         G = L^T H -> bf16 hi/lo planes
// ===========================================================================
#define PAD_D 513
#define PREP_BLOCKS 64
#define CONV_BLOCKS 192
#define TOTAL_PRE   (PREP_BLOCKS + CONV_BLOCKS)

__global__ __launch_bounds__(256) void pre_kernel(
    const float* __restrict__ high, const float* __restrict__ x)
{
    const int t = threadIdx.x;

    if (blockIdx.x >= PREP_BLOCKS) {
        // ---------------- convert branch ----------------
        if (blockIdx.x == PREP_BLOCKS) {
            for (int i = t; i < B_ * C_; i += 256) g_V[i] = 0.0f;
        }
        const int NB4 = Q_ * D_ / 4;    // 409600 float4 elements
        int idx = (blockIdx.x - PREP_BLOCKS) * 256 + t;
        const int stride = CONV_BLOCKS * 256;
        const float4* x4 = reinterpret_cast<const float4*>(x);
        __nv_bfloat162* bh2 = reinterpret_cast<__nv_bfloat162*>(g_Bhi);
        __nv_bfloat162* bl2 = reinterpret_cast<__nv_bfloat162*>(g_Blo);
        for (int i = idx; i < NB4; i += stride) {
            float4 v = x4[i];
            __nv_bfloat16 hx = __float2bfloat16(v.x);
            __nv_bfloat16 hy = __float2bfloat16(v.y);
            __nv_bfloat16 hz = __float2bfloat16(v.z);
            __nv_bfloat16 hw = __float2bfloat16(v.w);
            bh2[i * 2 + 0] = __nv_bfloat162(hx, hy);
            bh2[i * 2 + 1] = __nv_bfloat162(hz, hw);
            bl2[i * 2 + 0] = __nv_bfloat162(
                __float2bfloat16(v.x - __bfloat162float(hx)),
                __float2bfloat16(v.y - __bfloat162float(hy)));
            bl2[i * 2 + 1] = __nv_bfloat162(
                __float2bfloat16(v.z - __bfloat162float(hz)),
                __float2bfloat16(v.w - __bfloat162float(hw)));
        }
        return;
    }

    // ---------------- prep branch ----------------
    const int c = blockIdx.x;

    __shared__ float sH[N_ * PAD_D];
    __shared__ float aug[N_][2 * N_ + 1];
    __shared__ float colk[N_];
    __shared__ float sS[N_][N_ + 1];

    const float* Hc = high + (size_t)c * N_ * D_;
    for (int i = t; i < N_ * D_; i += 256) {
        int r = i / D_, k = i % D_;
        sH[r * PAD_D + k] = Hc[i];
    }
    __syncthreads();

    for (int e = t; e < N_ * N_; e += 256) {
        int i = e / N_, j = e % N_;
        const float* ri = sH + i * PAD_D;
        const float* rj = sH + j * PAD_D;
        float a0 = 0.f, a1 = 0.f, a2 = 0.f, a3 = 0.f;
        #pragma unroll 4
        for (int k = 0; k < D_; k += 4) {
            a0 = fmaf(ri[k + 0], rj[k + 0], a0);
            a1 = fmaf(ri[k + 1], rj[k + 1], a1);
            a2 = fmaf(ri[k + 2], rj[k + 2], a2);
            a3 = fmaf(ri[k + 3], rj[k + 3], a3);
        }
        float acc = (a0 + a1) + (a2 + a3);
        aug[i][j] = acc + (i == j ? LAM : 0.0f);
        aug[i][N_ + j] = (i == j) ? 1.0f : 0.0f;
    }
    __syncthreads();

    // Gauss-Jordan (SPD, no pivoting)
    for (int k = 0; k < N_; k++) {
        float pinv = 1.0f / aug[k][k];
        if (t < N_) colk[t] = aug[t][k];
        __syncthreads();
        if (t < 2 * N_) aug[k][t] *= pinv;
        __syncthreads();
        for (int e = t; e < N_ * 2 * N_; e += 256) {
            int i = e / (2 * N_), j = e % (2 * N_);
            if (i != k) aug[i][j] = fmaf(-colk[i], aug[k][j], aug[i][j]);
        }
        __syncthreads();
    }

    // S = M + lam * M*M
    for (int e = t; e < N_ * N_; e += 256) {
        int i = e / N_, j = e % N_;
        float acc = 0.0f;
        #pragma unroll
        for (int k = 0; k < N_; k++) acc = fmaf(aug[i][N_ + k], aug[k][N_ + j], acc);
        sS[i][j] = aug[i][N_ + j] + LAM * acc;
    }
    __syncthreads();

    // In-place Cholesky (lower): S = L L^T
    for (int k = 0; k < N_; k++) {
        if (t == 0) sS[k][k] = sqrtf(sS[k][k]);
        __syncthreads();
        if (t > k && t < N_) sS[t][k] /= sS[k][k];
        __syncthreads();
        for (int e = t; e < N_ * N_; e += 256) {
            int i = e / N_, j = e % N_;
            if (j > k && i >= j) sS[i][j] = fmaf(-sS[i][k], sS[j][k], sS[i][j]);
        }
        __syncthreads();
    }

    // G = L^T H -> bf16 hi/lo planes
    __nv_bfloat16* Ahi = g_Ahi + (size_t)c * N_ * D_;
    __nv_bfloat16* Alo = g_Alo + (size_t)c * N_ * D_;
    for (int e = t; e < N_ * D_; e += 256) {
        int i = e / D_, kd = e % D_;
        float acc = 0.0f;
        for (int j = i; j < N_; j++)
            acc = fmaf(sS[j][i], sH[j * PAD_D + kd], acc);
        __nv_bfloat16 h = __float2bfloat16(acc);
        Ahi[e] = h;
        Alo[e] = __float2bfloat16(acc - __bfloat162float(h));
    }
}

// ===========================================================================
// Kernel 2: HMMA bf16x3 GEMM with FUSED sum-of-squares epilogue.
// Z = G_all(1280x512) * X^T computed per 128x128 tile (full K per block),
// epilogue squares fragments and reduces into g_V[b,c] via smem + atomics.
// ===========================================================================
#define BM   128
#define BN   128
#define BKc  32
#define NKC  (D_ / BKc)           // 16
#define ROWB 80                   // 64B data + 16B pad (conflict-free ldsm)
#define SZ_T (128 * ROWB)         // 10240 per plane
#define SA_HI 0
#define SA_LO SZ_T
#define SB_HI (2 * SZ_T)
#define SB_LO (3 * SZ_T)
#define STG   (4 * SZ_T)          // 40960 per stage
#define SM_TOTAL (2 * STG)        // 81920

__global__ __launch_bounds__(256) void gemm_kernel() {
    extern __shared__ char sm[];
    __shared__ float sV2[8][8];      // [class_local][b_local]
    const uint32_t sb = smem_to_u32(sm);
    const int tid = threadIdx.x;
    const int lane = tid & 31;
    const int wid = tid >> 5;
    const int wm = wid & 3;          // m offset 32*wm
    const int wn = wid >> 2;         // n offset 64*wn
    const int m0 = blockIdx.y * BM;
    const int n0 = blockIdx.x * BN;

    if (tid < 64) reinterpret_cast<float*>(sV2)[tid] = 0.0f;

    float acc[2][8][4];
    #pragma unroll
    for (int i = 0; i < 2; i++)
        #pragma unroll
        for (int j = 0; j < 8; j++)
            #pragma unroll
            for (int k = 0; k < 4; k++) acc[i][j][k] = 0.0f;

    const int ar0 = tid >> 2;            // 0..63
    const int ac4 = (tid & 3) * 16;      // byte offset of uint4 within 64B row
    const int ak8 = (tid & 3) * 8;       // element offset

    const int a_row  = wm * 32 + (lane & 15);
    const int a_kb   = ((lane >> 4) * 8) * 2;
    const uint32_t aoff = (uint32_t)(a_row * ROWB + a_kb);
    const int b_row  = wn * 64 + (lane & 7) + ((lane >> 4) * 8);
    const int b_kb   = (((lane >> 3) & 1) * 8) * 2;
    const uint32_t boff = (uint32_t)(b_row * ROWB + b_kb);

    auto load_stage = [&](int s, int kc) {
        const uint32_t base = sb + s * STG;
        const size_t kbase = (size_t)kc * BKc;
        #pragma unroll
        for (int p = 0; p < 2; p++) {
            int row = ar0 + p * 64;
            size_t ga = (size_t)(m0 + row) * D_ + kbase + ak8;
            size_t gb = (size_t)(n0 + row) * D_ + kbase + ak8;
            uint32_t soff = (uint32_t)(row * ROWB + ac4);
            CP_ASYNC16(base + SA_HI + soff, g_Ahi + ga);
            CP_ASYNC16(base + SA_LO + soff, g_Alo + ga);
            CP_ASYNC16(base + SB_HI + soff, g_Bhi + gb);
            CP_ASYNC16(base + SB_LO + soff, g_Blo + gb);
        }
    };

    load_stage(0, 0); CP_COMMIT();
    load_stage(1, 1); CP_COMMIT();

    for (int kc = 0; kc < NKC; kc++) {
        const int s = kc & 1;
        if (kc + 1 < NKC) { CP_WAIT(1); } else { CP_WAIT(0); }
        __syncthreads();

        const uint32_t base = sb + s * STG;
        #pragma unroll
        for (int ks = 0; ks < 2; ks++) {
            const uint32_t kb = ks * 32;
            uint32_t ah0[4], ah1[4], al0[4], al1[4];
            ldsm_x4(ah0, base + SA_HI + aoff + kb);
            ldsm_x4(ah1, base + SA_HI + aoff + 16 * ROWB + kb);
            ldsm_x4(al0, base + SA_LO + aoff + kb);
            ldsm_x4(al1, base + SA_LO + aoff + 16 * ROWB + kb);

            uint32_t Bh[8][2], Bl[8][2];
            #pragma unroll
            for (int g = 0; g < 4; g++) {
                uint32_t bh[4], bl[4];
                ldsm_x4(bh, base + SB_HI + boff + g * 16 * ROWB + kb);
                ldsm_x4(bl, base + SB_LO + boff + g * 16 * ROWB + kb);
                Bh[g * 2 + 0][0] = bh[0]; Bh[g * 2 + 0][1] = bh[1];
                Bh[g * 2 + 1][0] = bh[2]; Bh[g * 2 + 1][1] = bh[3];
                Bl[g * 2 + 0][0] = bl[0]; Bl[g * 2 + 0][1] = bl[1];
                Bl[g * 2 + 1][0] = bl[2]; Bl[g * 2 + 1][1] = bl[3];
            }

            #pragma unroll
            for (int nt = 0; nt < 8; nt++) {
                mma16816(acc[0][nt], ah0, Bh[nt][0], Bh[nt][1]);
                mma16816(acc[1][nt], ah1, Bh[nt][0], Bh[nt][1]);
                mma16816(acc[0][nt], al0, Bh[nt][0], Bh[nt][1]);
                mma16816(acc[1][nt], al1, Bh[nt][0], Bh[nt][1]);
                mma16816(acc[0][nt], ah0, Bl[nt][0], Bl[nt][1]);
                mma16816(acc[1][nt], ah1, Bl[nt][0], Bl[nt][1]);
            }
        }
        __syncthreads();

        if (kc + 2 < NKC) { load_stage(s, kc + 2); CP_COMMIT(); }
    }

    // ---- fused epilogue: V[b,c] += z^2 ----
    const int gr = lane >> 2;
    const int gc = (lane & 3) * 2;
    const int c0 = m0 / N_;      // first class in this tile
    const int b0 = n0 / RES_;    // first batch in this tile
    __syncthreads();             // sV2 zeroed + mainloop smem done

    #pragma unroll
    for (int mt = 0; mt < 2; mt++) {
        #pragma unroll
        for (int hh = 0; hh < 2; hh++) {
            const int row = m0 + wm * 32 + mt * 16 + gr + hh * 8;
            const int cl = row / N_ - c0;
            #pragma unroll
            for (int nt = 0; nt < 8; nt++) {
                const int col = n0 + wn * 64 + nt * 8 + gc;
                float z0 = acc[mt][nt][2 * hh + 0];
                float z1 = acc[mt][nt][2 * hh + 1];
                atomicAdd(&sV2[cl][col / RES_ - b0], z0 * z0);
                atomicAdd(&sV2[cl][(col + 1) / RES_ - b0], z1 * z1);
            }
        }
    }
    __syncthreads();

    if (tid < 64) {
        const int cl = tid >> 3, bl = tid & 7;
        const int c = c0 + cl, b = b0 + bl;
        if (c < C_ && b < B_) {
            float v = sV2[cl][bl];
            if (v != 0.0f) atomicAdd(&g_V[b * C_ + c], v);
        }
    }
}

// ===========================================================================
// Kernel 3: per-b min-max scale.
// ===========================================================================
__global__ __launch_bounds__(64) void minmax_kernel(float* __restrict__ out) {
    const int b = blockIdx.x;
    const int t = threadIdx.x;
    const int lane = t & 31;
    const int w = t >> 5;

    __shared__ float sMn[2], sMx[2];

    float v = g_V[b * C_ + t];
    float mn = v, mx = v;
    #pragma unroll
    for (int off = 16; off > 0; off >>= 1) {
        mn = fminf(mn, __shfl_xor_sync(0xffffffffu, mn, off));
        mx = fmaxf(mx, __shfl_xor_sync(0xffffffffu, mx, off));
    }
    if (lane == 0) { sMn[w] = mn; sMx[w] = mx; }
    __syncthreads();
    float gmn = fminf(sMn[0], sMn[1]);
    float gmx = fmaxf(sMx[0], sMx[1]);

    out[b * C_ + t] = (v - gmn) / (gmx - gmn);
}

// ===========================================================================
extern "C" void kernel_launch(void* const* d_in, const int* in_sizes, int n_in,
                              void* d_out, int out_size) {
    const float* x    = (const float*)d_in[0];   // (128, 25, 512)
    const float* high = (const float*)d_in[1];   // (64, 20, 512)
    float* out = (float*)d_out;                  // (128, 64)

    cudaFuncSetAttribute(gemm_kernel,
                         cudaFuncAttributeMaxDynamicSharedMemorySize, SM_TOTAL);

    pre_kernel<<<TOTAL_PRE, 256>>>(high, x);

    dim3 grid(Q_ / BN, M_ROWS / BM);             // (25, 10)
    gemm_kernel<<<grid, 256, SM_TOTAL>>>();

    minmax_kernel<<<B_, 64>>>(out);
}

// round 11
// speedup vs baseline: 3.0552x; 3.0552x over previous
#include <cuda_runtime.h>
#include <cuda_bf16.h>
#include <cstdint>

// ===========================================================================
// Problem constants
// ===========================================================================
#define B_      128
#define RES_    25
#define D_      512
#define C_      64
#define N_      20
#define Q_      (B_ * RES_)      // 3200
#define M_ROWS  (C_ * N_)        // 1280
#define LAM     (20.0f / 512.0f)

// ===========================================================================
// Device scratch (allocation-free)
// ===========================================================================
__device__ float g_Y[M_ROWS * Q_];                 // 1280 x 3200 fp32 (Z = G X^T)
__device__ float g_V[B_ * C_];                     // 128 x 64 quadform sums
__device__ __nv_bfloat16 g_Ahi[M_ROWS * D_];       // G hi/lo planes (prep)
__device__ __nv_bfloat16 g_Alo[M_ROWS * D_];
__device__ __nv_bfloat16 g_Bhi[Q_ * D_];           // x hi/lo planes (convert)
__device__ __nv_bfloat16 g_Blo[Q_ * D_];

// ===========================================================================
// PTX helpers
// ===========================================================================
__device__ __forceinline__ uint32_t smem_to_u32(const void* p) {
    uint32_t a;
    asm("{ .reg .u64 t; cvta.to.shared.u64 t, %1; cvt.u32.u64 %0, t; }"
        : "=r"(a) : "l"(p));
    return a;
}

#define CP_ASYNC16(dst_u32, src_ptr) \
    asm volatile("cp.async.cg.shared.global [%0], [%1], 16;" \
        :: "r"(dst_u32), "l"(src_ptr) : "memory")
#define CP_COMMIT() asm volatile("cp.async.commit_group;" ::: "memory")
#define CP_WAIT(n)  asm volatile("cp.async.wait_group %0;" :: "n"(n) : "memory")

__device__ __forceinline__ void ldsm_x4(uint32_t r[4], uint32_t addr) {
    asm volatile("ldmatrix.sync.aligned.m8n8.x4.shared.b16 {%0,%1,%2,%3}, [%4];"
        : "=r"(r[0]), "=r"(r[1]), "=r"(r[2]), "=r"(r[3]) : "r"(addr));
}

__device__ __forceinline__ void mma16816(float c[4], const uint32_t a[4],
                                         uint32_t b0, uint32_t b1) {
    asm volatile(
        "mma.sync.aligned.m16n8k16.row.col.f32.bf16.bf16.f32 "
        "{%0,%1,%2,%3},{%4,%5,%6,%7},{%8,%9},{%0,%1,%2,%3};"
        : "+f"(c[0]), "+f"(c[1]), "+f"(c[2]), "+f"(c[3])
        : "r"(a[0]), "r"(a[1]), "r"(a[2]), "r"(a[3]), "r"(b0), "r"(b1));
}

// ===========================================================================
// Kernel 1: per-class prep, latency-optimized.
//   A = H H^T + lam*I  (warp-cooperative dot products)
//   M = A^-1 (Gauss-Jordan) ; S = M + lam*M^2 ; S = L L^T (Cholesky)
//   G = L^T H -> bf16 hi/lo planes (float4 smem reads)
// ===========================================================================
#define PAD_D 516   // multiple of 4 (float4) ; 516 % 32 = 4 -> conflict-free

__global__ __launch_bounds__(256) void prep_kernel(const float* __restrict__ high) {
    const int c = blockIdx.x;
    const int t = threadIdx.x;
    const int lane = t & 31;
    const int wid = t >> 5;

    __shared__ float sH[N_ * PAD_D];       // ~41.3 KB
    __shared__ float aug[N_][2 * N_ + 1];
    __shared__ float colk[N_];
    __shared__ float sS[N_][N_ + 1];

    // Stage H (float4 coalesced)
    const float4* H4 = reinterpret_cast<const float4*>(high + (size_t)c * N_ * D_);
    for (int idx = t; idx < N_ * D_ / 4; idx += 256) {
        int r = idx >> 7;            // 128 float4 per row
        int k4 = idx & 127;
        *reinterpret_cast<float4*>(&sH[r * PAD_D + k4 * 4]) = H4[idx];
    }
    // Identity half of aug
    for (int e = t; e < N_ * N_; e += 256) {
        int i = e / N_, j = e % N_;
        aug[i][N_ + j] = (i == j) ? 1.0f : 0.0f;
    }
    __syncthreads();

    // Warp-cooperative Gram: 210 unique pairs (i<=j), one pair per warp-round
    for (int p = wid; p < 210; p += 8) {
        int i = 0, rem = p;
        while (rem >= N_ - i) { rem -= N_ - i; i++; }
        int j = i + rem;
        const float* ri = sH + i * PAD_D;
        const float* rj = sH + j * PAD_D;
        float s0 = 0.f, s1 = 0.f;
        #pragma unroll
        for (int k = 0; k < 8; k++) {
            s0 = fmaf(ri[lane + k * 64],      rj[lane + k * 64],      s0);
            s1 = fmaf(ri[lane + 32 + k * 64], rj[lane + 32 + k * 64], s1);
        }
        float s = s0 + s1;
        #pragma unroll
        for (int off = 16; off > 0; off >>= 1)
            s += __shfl_xor_sync(0xffffffffu, s, off);
        if (lane == 0) {
            float v = s + (i == j ? LAM : 0.0f);
            aug[i][j] = v;
            if (i != j) aug[j][i] = v;
        }
    }
    __syncthreads();

    // Gauss-Jordan (SPD, no pivoting)
    for (int k = 0; k < N_; k++) {
        float pinv = 1.0f / aug[k][k];
        if (t < N_) colk[t] = aug[t][k];
        __syncthreads();
        if (t < 2 * N_) aug[k][t] *= pinv;
        __syncthreads();
        for (int e = t; e < N_ * 2 * N_; e += 256) {
            int i = e / (2 * N_), j = e % (2 * N_);
            if (i != k) aug[i][j] = fmaf(-colk[i], aug[k][j], aug[i][j]);
        }
        __syncthreads();
    }

    // S = M + lam * M*M
    for (int e = t; e < N_ * N_; e += 256) {
        int i = e / N_, j = e % N_;
        float acc = 0.0f;
        #pragma unroll
        for (int k = 0; k < N_; k++) acc = fmaf(aug[i][N_ + k], aug[k][N_ + j], acc);
        sS[i][j] = aug[i][N_ + j] + LAM * acc;
    }
    __syncthreads();

    // In-place Cholesky (lower): S = L L^T
    for (int k = 0; k < N_; k++) {
        if (t == 0) sS[k][k] = sqrtf(sS[k][k]);
        __syncthreads();
        if (t > k && t < N_) sS[t][k] /= sS[k][k];
        __syncthreads();
        for (int e = t; e < N_ * N_; e += 256) {
            int i = e / N_, j = e % N_;
            if (j > k && i >= j) sS[i][j] = fmaf(-sS[i][k], sS[j][k], sS[i][j]);
        }
        __syncthreads();
    }

    // G = L^T H -> bf16 hi/lo planes (float4 reads, bf162 stores).
    // Thread t owns float4 column kd4 = (t&127)*4, rows i = (t>>7) + 2r.
    const int kd4 = (t & 127) * 4;
    const int ihalf = t >> 7;
    __nv_bfloat162* Ahi2 = reinterpret_cast<__nv_bfloat162*>(g_Ahi + (size_t)c * N_ * D_);
    __nv_bfloat162* Alo2 = reinterpret_cast<__nv_bfloat162*>(g_Alo + (size_t)c * N_ * D_);
    #pragma unroll
    for (int r = 0; r < 10; r++) {
        const int i = ihalf + 2 * r;
        float ax = 0.f, ay = 0.f, az = 0.f, aw = 0.f;
        for (int j = i; j < N_; j++) {
            float lji = sS[j][i];
            float4 h = *reinterpret_cast<const float4*>(&sH[j * PAD_D + kd4]);
            ax = fmaf(lji, h.x, ax);
            ay = fmaf(lji, h.y, ay);
            az = fmaf(lji, h.z, az);
            aw = fmaf(lji, h.w, aw);
        }
        __nv_bfloat16 hx = __float2bfloat16(ax);
        __nv_bfloat16 hy = __float2bfloat16(ay);
        __nv_bfloat16 hz = __float2bfloat16(az);
        __nv_bfloat16 hw = __float2bfloat16(aw);
        const int base2 = (i * D_ + kd4) >> 1;   // bf162 index
        Ahi2[base2 + 0] = __nv_bfloat162(hx, hy);
        Ahi2[base2 + 1] = __nv_bfloat162(hz, hw);
        Alo2[base2 + 0] = __nv_bfloat162(
            __float2bfloat16(ax - __bfloat162float(hx)),
            __float2bfloat16(ay - __bfloat162float(hy)));
        Alo2[base2 + 1] = __nv_bfloat162(
            __float2bfloat16(az - __bfloat162float(hz)),
            __float2bfloat16(aw - __bfloat162float(hw)));
    }
}

// ===========================================================================
// Kernel 2: fp32 x -> bf16 hi/lo planes (float4-vectorized, no smem)
// ===========================================================================
__global__ __launch_bounds__(256) void convert_kernel(const float* __restrict__ x)
{
    const int NB4 = Q_ * D_ / 4;
    int idx = blockIdx.x * 256 + threadIdx.x;
    const int stride = gridDim.x * 256;
    const float4* x4 = reinterpret_cast<const float4*>(x);
    __nv_bfloat162* bh2 = reinterpret_cast<__nv_bfloat162*>(g_Bhi);
    __nv_bfloat162* bl2 = reinterpret_cast<__nv_bfloat162*>(g_Blo);
    for (int i = idx; i < NB4; i += stride) {
        float4 v = x4[i];
        __nv_bfloat16 hx = __float2bfloat16(v.x);
        __nv_bfloat16 hy = __float2bfloat16(v.y);
        __nv_bfloat16 hz = __float2bfloat16(v.z);
        __nv_bfloat16 hw = __float2bfloat16(v.w);
        bh2[i * 2 + 0] = __nv_bfloat162(hx, hy);
        bh2[i * 2 + 1] = __nv_bfloat162(hz, hw);
        bl2[i * 2 + 0] = __nv_bfloat162(
            __float2bfloat16(v.x - __bfloat162float(hx)),
            __float2bfloat16(v.y - __bfloat162float(hy)));
        bl2[i * 2 + 1] = __nv_bfloat162(
            __float2bfloat16(v.z - __bfloat162float(hz)),
            __float2bfloat16(v.w - __bfloat162float(hw)));
    }
}

// ===========================================================================
// Kernel 3: HMMA bf16x3 GEMM (identical to the 86.6us R9 version).
// Z = G_all(1280x512) * X^T, tile 128x128, 3 MMAs per k-step.
// ===========================================================================
#define BM   128
#define BN   128
#define BKc  32
#define NKC  (D_ / BKc)           // 16
#define ROWB 80
#define SZ_T (128 * ROWB)
#define SA_HI 0
#define SA_LO SZ_T
#define SB_HI (2 * SZ_T)
#define SB_LO (3 * SZ_T)
#define STG   (4 * SZ_T)          // 40960
#define SM_TOTAL (2 * STG)        // 81920

__global__ __launch_bounds__(256) void gemm_kernel() {
    extern __shared__ char sm[];
    const uint32_t sb = smem_to_u32(sm);
    const int tid = threadIdx.x;
    const int lane = tid & 31;
    const int wid = tid >> 5;
    const int wm = wid & 3;
    const int wn = wid >> 2;
    const int m0 = blockIdx.y * BM;
    const int n0 = blockIdx.x * BN;

    float acc[2][8][4];
    #pragma unroll
    for (int i = 0; i < 2; i++)
        #pragma unroll
        for (int j = 0; j < 8; j++)
            #pragma unroll
            for (int k = 0; k < 4; k++) acc[i][j][k] = 0.0f;

    const int ar0 = tid >> 2;
    const int ac4 = (tid & 3) * 16;
    const int ak8 = (tid & 3) * 8;

    const int a_row  = wm * 32 + (lane & 15);
    const int a_kb   = ((lane >> 4) * 8) * 2;
    const uint32_t aoff = (uint32_t)(a_row * ROWB + a_kb);
    const int b_row  = wn * 64 + (lane & 7) + ((lane >> 4) * 8);
    const int b_kb   = (((lane >> 3) & 1) * 8) * 2;
    const uint32_t boff = (uint32_t)(b_row * ROWB + b_kb);

    auto load_stage = [&](int s, int kc) {
        const uint32_t base = sb + s * STG;
        const size_t kbase = (size_t)kc * BKc;
        #pragma unroll
        for (int p = 0; p < 2; p++) {
            int row = ar0 + p * 64;
            size_t ga = (size_t)(m0 + row) * D_ + kbase + ak8;
            size_t gb = (size_t)(n0 + row) * D_ + kbase + ak8;
            uint32_t soff = (uint32_t)(row * ROWB + ac4);
            CP_ASYNC16(base + SA_HI + soff, g_Ahi + ga);
            CP_ASYNC16(base + SA_LO + soff, g_Alo + ga);
            CP_ASYNC16(base + SB_HI + soff, g_Bhi + gb);
            CP_ASYNC16(base + SB_LO + soff, g_Blo + gb);
        }
    };

    load_stage(0, 0); CP_COMMIT();
    load_stage(1, 1); CP_COMMIT();

    for (int kc = 0; kc < NKC; kc++) {
        const int s = kc & 1;
        if (kc + 1 < NKC) { CP_WAIT(1); } else { CP_WAIT(0); }
        __syncthreads();

        const uint32_t base = sb + s * STG;
        #pragma unroll
        for (int ks = 0; ks < 2; ks++) {
            const uint32_t kb = ks * 32;
            uint32_t ah0[4], ah1[4], al0[4], al1[4];
            ldsm_x4(ah0, base + SA_HI + aoff + kb);
            ldsm_x4(ah1, base + SA_HI + aoff + 16 * ROWB + kb);
            ldsm_x4(al0, base + SA_LO + aoff + kb);
            ldsm_x4(al1, base + SA_LO + aoff + 16 * ROWB + kb);

            uint32_t Bh[8][2], Bl[8][2];
            #pragma unroll
            for (int g = 0; g < 4; g++) {
                uint32_t bh[4], bl[4];
                ldsm_x4(bh, base + SB_HI + boff + g * 16 * ROWB + kb);
                ldsm_x4(bl, base + SB_LO + boff + g * 16 * ROWB + kb);
                Bh[g * 2 + 0][0] = bh[0]; Bh[g * 2 + 0][1] = bh[1];
                Bh[g * 2 + 1][0] = bh[2]; Bh[g * 2 + 1][1] = bh[3];
                Bl[g * 2 + 0][0] = bl[0]; Bl[g * 2 + 0][1] = bl[1];
                Bl[g * 2 + 1][0] = bl[2]; Bl[g * 2 + 1][1] = bl[3];
            }

            #pragma unroll
            for (int nt = 0; nt < 8; nt++) {
                mma16816(acc[0][nt], ah0, Bh[nt][0], Bh[nt][1]);
                mma16816(acc[1][nt], ah1, Bh[nt][0], Bh[nt][1]);
                mma16816(acc[0][nt], al0, Bh[nt][0], Bh[nt][1]);
                mma16816(acc[1][nt], al1, Bh[nt][0], Bh[nt][1]);
                mma16816(acc[0][nt], ah0, Bl[nt][0], Bl[nt][1]);
                mma16816(acc[1][nt], ah1, Bl[nt][0], Bl[nt][1]);
            }
        }
        __syncthreads();

        if (kc + 2 < NKC) { load_stage(s, kc + 2); CP_COMMIT(); }
    }

    const int gr = lane >> 2;
    const int gc = (lane & 3) * 2;
    #pragma unroll
    for (int mt = 0; mt < 2; mt++) {
        const int rbase = m0 + wm * 32 + mt * 16 + gr;
        #pragma unroll
        for (int nt = 0; nt < 8; nt++) {
            const int col = n0 + wn * 64 + nt * 8 + gc;
            float2 v0 = {acc[mt][nt][0], acc[mt][nt][1]};
            float2 v1 = {acc[mt][nt][2], acc[mt][nt][3]};
            *reinterpret_cast<float2*>(g_Y + (size_t)rbase * Q_ + col) = v0;
            *reinterpret_cast<float2*>(g_Y + (size_t)(rbase + 8) * Q_ + col) = v1;
        }
    }
}

// ===========================================================================
// Kernel 4a: sum-of-squares quadforms.  V[b,c] = sum_{i,r} Z[c*20+i, b*25+r]^2
// ===========================================================================
__global__ __launch_bounds__(256) void quadv_kernel() {
    const int b  = blockIdx.x;
    const int cg = blockIdx.y;
    const int wid = threadIdx.x >> 5;
    const int lane = threadIdx.x & 31;
    const int c = cg * 8 + wid;

    float acc = 0.0f;
    if (lane < RES_) {
        const size_t q = (size_t)b * RES_ + lane;
        const float* base = g_Y + (size_t)c * N_ * Q_ + q;
        #pragma unroll
        for (int i = 0; i < N_; i++) {
            float v = base[(size_t)i * Q_];
            acc = fmaf(v, v, acc);
        }
    }
    #pragma unroll
    for (int off = 16; off > 0; off >>= 1)
        acc += __shfl_down_sync(0xffffffffu, acc, off);
    if (lane == 0) g_V[b * C_ + c] = acc;
}

// ===========================================================================
// Kernel 4b: per-b min-max scale.
// ===========================================================================
__global__ __launch_bounds__(64) void minmax_kernel(float* __restrict__ out) {
    const int b = blockIdx.x;
    const int t = threadIdx.x;
    const int lane = t & 31;
    const int w = t >> 5;

    __shared__ float sMn[2], sMx[2];

    float v = g_V[b * C_ + t];
    float mn = v, mx = v;
    #pragma unroll
    for (int off = 16; off > 0; off >>= 1) {
        mn = fminf(mn, __shfl_xor_sync(0xffffffffu, mn, off));
        mx = fmaxf(mx, __shfl_xor_sync(0xffffffffu, mx, off));
    }
    if (lane == 0) { sMn[w] = mn; sMx[w] = mx; }
    __syncthreads();
    float gmn = fminf(sMn[0], sMn[1]);
    float gmx = fmaxf(sMx[0], sMx[1]);

    out[b * C_ + t] = (v - gmn) / (gmx - gmn);
}

// ===========================================================================
extern "C" void kernel_launch(void* const* d_in, const int* in_sizes, int n_in,
                              void* d_out, int out_size) {
    const float* x    = (const float*)d_in[0];   // (128, 25, 512)
    const float* high = (const float*)d_in[1];   // (64, 20, 512)
    float* out = (float*)d_out;                  // (128, 64)

    cudaFuncSetAttribute(gemm_kernel,
                         cudaFuncAttributeMaxDynamicSharedMemorySize, SM_TOTAL);

    convert_kernel<<<800, 256>>>(x);
    prep_kernel<<<C_, 256>>>(high);

    dim3 grid(Q_ / BN, M_ROWS / BM);             // (25, 10)
    gemm_kernel<<<grid, 256, SM_TOTAL>>>();

    dim3 qgrid(B_, C_ / 8);                      // (128, 8)
    quadv_kernel<<<qgrid, 256>>>();
    minmax_kernel<<<B_, 64>>>(out);
}

// round 12
// speedup vs baseline: 3.5736x; 1.1697x over previous
#include <cuda_runtime.h>
#include <cuda_fp16.h>
#include <cstdint>

// ===========================================================================
// Problem constants
// ===========================================================================
#define B_      128
#define RES_    25
#define D_      512
#define C_      64
#define N_      20
#define Q_      (B_ * RES_)      // 3200
#define M_ROWS  (C_ * N_)        // 1280
#define LAM     (20.0f / 512.0f)
#define ASCALE  2048.0f          // A pre-scale (keeps Alo in fp16 normal range)

// ===========================================================================
// Device scratch (allocation-free)
// ===========================================================================
__device__ float g_Y[M_ROWS * Q_];        // 1280 x 3200 fp32 (Z = G X^T)
__device__ float g_V[B_ * C_];            // 128 x 64 quadform sums
__device__ __half g_Ahi[M_ROWS * D_];     // G*2048 fp16 hi/lo planes (prep)
__device__ __half g_Alo[M_ROWS * D_];
__device__ __half g_Bf[Q_ * D_];          // x fp16 plane (convert)

// ===========================================================================
// PTX helpers
// ===========================================================================
__device__ __forceinline__ uint32_t smem_to_u32(const void* p) {
    uint32_t a;
    asm("{ .reg .u64 t; cvta.to.shared.u64 t, %1; cvt.u32.u64 %0, t; }"
        : "=r"(a) : "l"(p));
    return a;
}

#define CP_ASYNC16(dst_u32, src_ptr) \
    asm volatile("cp.async.cg.shared.global [%0], [%1], 16;" \
        :: "r"(dst_u32), "l"(src_ptr) : "memory")
#define CP_COMMIT() asm volatile("cp.async.commit_group;" ::: "memory")
#define CP_WAIT(n)  asm volatile("cp.async.wait_group %0;" :: "n"(n) : "memory")

__device__ __forceinline__ void ldsm_x4(uint32_t r[4], uint32_t addr) {
    asm volatile("ldmatrix.sync.aligned.m8n8.x4.shared.b16 {%0,%1,%2,%3}, [%4];"
        : "=r"(r[0]), "=r"(r[1]), "=r"(r[2]), "=r"(r[3]) : "r"(addr));
}

__device__ __forceinline__ void mma16816h(float c[4], const uint32_t a[4],
                                          uint32_t b0, uint32_t b1) {
    asm volatile(
        "mma.sync.aligned.m16n8k16.row.col.f32.f16.f16.f32 "
        "{%0,%1,%2,%3},{%4,%5,%6,%7},{%8,%9},{%0,%1,%2,%3};"
        : "+f"(c[0]), "+f"(c[1]), "+f"(c[2]), "+f"(c[3])
        : "r"(a[0]), "r"(a[1]), "r"(a[2]), "r"(a[3]), "r"(b0), "r"(b1));
}

// ===========================================================================
// Kernel 1: per-class prep (warp-coop Gram; GJ inverse; S; Cholesky; G emit)
// G emitted as fp16 hi/lo planes of 2048*G.
// ===========================================================================
#define PAD_D 516   // multiple of 4 ; 516 % 32 = 4 -> conflict-free

__global__ __launch_bounds__(256) void prep_kernel(const float* __restrict__ high) {
    const int c = blockIdx.x;
    const int t = threadIdx.x;
    const int lane = t & 31;
    const int wid = t >> 5;

    __shared__ float sH[N_ * PAD_D];
    __shared__ float aug[N_][2 * N_ + 1];
    __shared__ float colk[N_];
    __shared__ float sS[N_][N_ + 1];

    const float4* H4 = reinterpret_cast<const float4*>(high + (size_t)c * N_ * D_);
    for (int idx = t; idx < N_ * D_ / 4; idx += 256) {
        int r = idx >> 7;
        int k4 = idx & 127;
        *reinterpret_cast<float4*>(&sH[r * PAD_D + k4 * 4]) = H4[idx];
    }
    for (int e = t; e < N_ * N_; e += 256) {
        int i = e / N_, j = e % N_;
        aug[i][N_ + j] = (i == j) ? 1.0f : 0.0f;
    }
    __syncthreads();

    // Warp-cooperative Gram: 210 unique pairs (i<=j)
    for (int p = wid; p < 210; p += 8) {
        int i = 0, rem = p;
        while (rem >= N_ - i) { rem -= N_ - i; i++; }
        int j = i + rem;
        const float* ri = sH + i * PAD_D;
        const float* rj = sH + j * PAD_D;
        float s0 = 0.f, s1 = 0.f;
        #pragma unroll
        for (int k = 0; k < 8; k++) {
            s0 = fmaf(ri[lane + k * 64],      rj[lane + k * 64],      s0);
            s1 = fmaf(ri[lane + 32 + k * 64], rj[lane + 32 + k * 64], s1);
        }
        float s = s0 + s1;
        #pragma unroll
        for (int off = 16; off > 0; off >>= 1)
            s += __shfl_xor_sync(0xffffffffu, s, off);
        if (lane == 0) {
            float v = s + (i == j ? LAM : 0.0f);
            aug[i][j] = v;
            if (i != j) aug[j][i] = v;
        }
    }
    __syncthreads();

    // Gauss-Jordan (SPD)
    for (int k = 0; k < N_; k++) {
        float pinv = 1.0f / aug[k][k];
        if (t < N_) colk[t] = aug[t][k];
        __syncthreads();
        if (t < 2 * N_) aug[k][t] *= pinv;
        __syncthreads();
        for (int e = t; e < N_ * 2 * N_; e += 256) {
            int i = e / (2 * N_), j = e % (2 * N_);
            if (i != k) aug[i][j] = fmaf(-colk[i], aug[k][j], aug[i][j]);
        }
        __syncthreads();
    }

    // S = M + lam * M*M
    for (int e = t; e < N_ * N_; e += 256) {
        int i = e / N_, j = e % N_;
        float acc = 0.0f;
        #pragma unroll
        for (int k = 0; k < N_; k++) acc = fmaf(aug[i][N_ + k], aug[k][N_ + j], acc);
        sS[i][j] = aug[i][N_ + j] + LAM * acc;
    }
    __syncthreads();

    // Cholesky (lower): S = L L^T
    for (int k = 0; k < N_; k++) {
        if (t == 0) sS[k][k] = sqrtf(sS[k][k]);
        __syncthreads();
        if (t > k && t < N_) sS[t][k] /= sS[k][k];
        __syncthreads();
        for (int e = t; e < N_ * N_; e += 256) {
            int i = e / N_, j = e % N_;
            if (j > k && i >= j) sS[i][j] = fmaf(-sS[i][k], sS[j][k], sS[i][j]);
        }
        __syncthreads();
    }

    // G = L^T H -> fp16 hi/lo planes of 2048*G
    const int kd4 = (t & 127) * 4;
    const int ihalf = t >> 7;
    __half2* Ahi2 = reinterpret_cast<__half2*>(g_Ahi + (size_t)c * N_ * D_);
    __half2* Alo2 = reinterpret_cast<__half2*>(g_Alo + (size_t)c * N_ * D_);
    #pragma unroll
    for (int r = 0; r < 10; r++) {
        const int i = ihalf + 2 * r;
        float ax = 0.f, ay = 0.f, az = 0.f, aw = 0.f;
        for (int j = i; j < N_; j++) {
            float lji = sS[j][i];
            float4 h = *reinterpret_cast<const float4*>(&sH[j * PAD_D + kd4]);
            ax = fmaf(lji, h.x, ax);
            ay = fmaf(lji, h.y, ay);
            az = fmaf(lji, h.z, az);
            aw = fmaf(lji, h.w, aw);
        }
        ax *= ASCALE; ay *= ASCALE; az *= ASCALE; aw *= ASCALE;
        __half hx = __float2half_rn(ax);
        __half hy = __float2half_rn(ay);
        __half hz = __float2half_rn(az);
        __half hw = __float2half_rn(aw);
        const int base2 = (i * D_ + kd4) >> 1;
        Ahi2[base2 + 0] = __half2(hx, hy);
        Ahi2[base2 + 1] = __half2(hz, hw);
        Alo2[base2 + 0] = __half2(
            __float2half_rn(ax - __half2float(hx)),
            __float2half_rn(ay - __half2float(hy)));
        Alo2[base2 + 1] = __half2(
            __float2half_rn(az - __half2float(hz)),
            __float2half_rn(aw - __half2float(hw)));
    }
}

// ===========================================================================
// Kernel 2: fp32 x -> single fp16 plane
// ===========================================================================
__global__ __launch_bounds__(256) void convert_kernel(const float* __restrict__ x)
{
    const int NB4 = Q_ * D_ / 4;
    int idx = blockIdx.x * 256 + threadIdx.x;
    const int stride = gridDim.x * 256;
    const float4* x4 = reinterpret_cast<const float4*>(x);
    __half2* b2 = reinterpret_cast<__half2*>(g_Bf);
    for (int i = idx; i < NB4; i += stride) {
        float4 v = x4[i];
        b2[i * 2 + 0] = __half2(__float2half_rn(v.x), __float2half_rn(v.y));
        b2[i * 2 + 1] = __half2(__float2half_rn(v.z), __float2half_rn(v.w));
    }
}

// ===========================================================================
// Kernel 3: HMMA fp16x2 GEMM.  Z = G_all(1280x512) * X^T.
// Tile 128x128, 2 MMAs per k-step (Ahi*B + Alo*B), fp32 accumulate.
// Epilogue scales by 1/2048.
// ===========================================================================
#define BM   128
#define BN   128
#define BKc  32
#define NKC  (D_ / BKc)           // 16
#define ROWB 80
#define SZ_T (128 * ROWB)         // 10240
#define SA_HI 0
#define SA_LO SZ_T
#define SB_F  (2 * SZ_T)
#define STG   (3 * SZ_T)          // 30720
#define SM_TOTAL (2 * STG)        // 61440

__global__ __launch_bounds__(256) void gemm_kernel() {
    extern __shared__ char sm[];
    const uint32_t sb = smem_to_u32(sm);
    const int tid = threadIdx.x;
    const int lane = tid & 31;
    const int wid = tid >> 5;
    const int wm = wid & 3;
    const int wn = wid >> 2;
    const int m0 = blockIdx.y * BM;
    const int n0 = blockIdx.x * BN;

    float acc[2][8][4];
    #pragma unroll
    for (int i = 0; i < 2; i++)
        #pragma unroll
        for (int j = 0; j < 8; j++)
            #pragma unroll
            for (int k = 0; k < 4; k++) acc[i][j][k] = 0.0f;

    const int ar0 = tid >> 2;
    const int ac4 = (tid & 3) * 16;
    const int ak8 = (tid & 3) * 8;

    const int a_row  = wm * 32 + (lane & 15);
    const int a_kb   = ((lane >> 4) * 8) * 2;
    const uint32_t aoff = (uint32_t)(a_row * ROWB + a_kb);
    const int b_row  = wn * 64 + (lane & 7) + ((lane >> 4) * 8);
    const int b_kb   = (((lane >> 3) & 1) * 8) * 2;
    const uint32_t boff = (uint32_t)(b_row * ROWB + b_kb);

    auto load_stage = [&](int s, int kc) {
        const uint32_t base = sb + s * STG;
        const size_t kbase = (size_t)kc * BKc;
        #pragma unroll
        for (int p = 0; p < 2; p++) {
            int row = ar0 + p * 64;
            size_t ga = (size_t)(m0 + row) * D_ + kbase + ak8;
            size_t gb = (size_t)(n0 + row) * D_ + kbase + ak8;
            uint32_t soff = (uint32_t)(row * ROWB + ac4);
            CP_ASYNC16(base + SA_HI + soff, g_Ahi + ga);
            CP_ASYNC16(base + SA_LO + soff, g_Alo + ga);
            CP_ASYNC16(base + SB_F  + soff, g_Bf  + gb);
        }
    };

    load_stage(0, 0); CP_COMMIT();
    load_stage(1, 1); CP_COMMIT();

    for (int kc = 0; kc < NKC; kc++) {
        const int s = kc & 1;
        if (kc + 1 < NKC) { CP_WAIT(1); } else { CP_WAIT(0); }
        __syncthreads();

        const uint32_t base = sb + s * STG;
        #pragma unroll
        for (int ks = 0; ks < 2; ks++) {
            const uint32_t kb = ks * 32;
            uint32_t ah0[4], ah1[4], al0[4], al1[4];
            ldsm_x4(ah0, base + SA_HI + aoff + kb);
            ldsm_x4(ah1, base + SA_HI + aoff + 16 * ROWB + kb);
            ldsm_x4(al0, base + SA_LO + aoff + kb);
            ldsm_x4(al1, base + SA_LO + aoff + 16 * ROWB + kb);

            uint32_t Bf[8][2];
            #pragma unroll
            for (int g = 0; g < 4; g++) {
                uint32_t bf[4];
                ldsm_x4(bf, base + SB_F + boff + g * 16 * ROWB + kb);
                Bf[g * 2 + 0][0] = bf[0]; Bf[g * 2 + 0][1] = bf[1];
                Bf[g * 2 + 1][0] = bf[2]; Bf[g * 2 + 1][1] = bf[3];
            }

            #pragma unroll
            for (int nt = 0; nt < 8; nt++) {
                mma16816h(acc[0][nt], ah0, Bf[nt][0], Bf[nt][1]);
                mma16816h(acc[1][nt], ah1, Bf[nt][0], Bf[nt][1]);
                mma16816h(acc[0][nt], al0, Bf[nt][0], Bf[nt][1]);
                mma16816h(acc[1][nt], al1, Bf[nt][0], Bf[nt][1]);
            }
        }
        __syncthreads();

        if (kc + 2 < NKC) { load_stage(s, kc + 2); CP_COMMIT(); }
    }

    const float inv = 1.0f / ASCALE;
    const int gr = lane >> 2;
    const int gc = (lane & 3) * 2;
    #pragma unroll
    for (int mt = 0; mt < 2; mt++) {
        const int rbase = m0 + wm * 32 + mt * 16 + gr;
        #pragma unroll
        for (int nt = 0; nt < 8; nt++) {
            const int col = n0 + wn * 64 + nt * 8 + gc;
            float2 v0 = {acc[mt][nt][0] * inv, acc[mt][nt][1] * inv};
            float2 v1 = {acc[mt][nt][2] * inv, acc[mt][nt][3] * inv};
            *reinterpret_cast<float2*>(g_Y + (size_t)rbase * Q_ + col) = v0;
            *reinterpret_cast<float2*>(g_Y + (size_t)(rbase + 8) * Q_ + col) = v1;
        }
    }
}

// ===========================================================================
// Kernel 4a: sum-of-squares quadforms.
// ===========================================================================
__global__ __launch_bounds__(256) void quadv_kernel() {
    const int b  = blockIdx.x;
    const int cg = blockIdx.y;
    const int wid = threadIdx.x >> 5;
    const int lane = threadIdx.x & 31;
    const int c = cg * 8 + wid;

    float acc = 0.0f;
    if (lane < RES_) {
        const size_t q = (size_t)b * RES_ + lane;
        const float* base = g_Y + (size_t)c * N_ * Q_ + q;
        #pragma unroll
        for (int i = 0; i < N_; i++) {
            float v = base[(size_t)i * Q_];
            acc = fmaf(v, v, acc);
        }
    }
    #pragma unroll
    for (int off = 16; off > 0; off >>= 1)
        acc += __shfl_down_sync(0xffffffffu, acc, off);
    if (lane == 0) g_V[b * C_ + c] = acc;
}

// ===========================================================================
// Kernel 4b: per-b min-max scale.
// ===========================================================================
__global__ __launch_bounds__(64) void minmax_kernel(float* __restrict__ out) {
    const int b = blockIdx.x;
    const int t = threadIdx.x;
    const int lane = t & 31;
    const int w = t >> 5;

    __shared__ float sMn[2], sMx[2];

    float v = g_V[b * C_ + t];
    float mn = v, mx = v;
    #pragma unroll
    for (int off = 16; off > 0; off >>= 1) {
        mn = fminf(mn, __shfl_xor_sync(0xffffffffu, mn, off));
        mx = fmaxf(mx, __shfl_xor_sync(0xffffffffu, mx, off));
    }
    if (lane == 0) { sMn[w] = mn; sMx[w] = mx; }
    __syncthreads();
    float gmn = fminf(sMn[0], sMn[1]);
    float gmx = fmaxf(sMx[0], sMx[1]);

    out[b * C_ + t] = (v - gmn) / (gmx - gmn);
}

// ===========================================================================
extern "C" void kernel_launch(void* const* d_in, const int* in_sizes, int n_in,
                              void* d_out, int out_size) {
    const float* x    = (const float*)d_in[0];   // (128, 25, 512)
    const float* high = (const float*)d_in[1];   // (64, 20, 512)
    float* out = (float*)d_out;                  // (128, 64)

    cudaFuncSetAttribute(gemm_kernel,
                         cudaFuncAttributeMaxDynamicSharedMemorySize, SM_TOTAL);

    convert_kernel<<<800, 256>>>(x);
    prep_kernel<<<C_, 256>>>(high);

    dim3 grid(Q_ / BN, M_ROWS / BM);             // (25, 10)
    gemm_kernel<<<grid, 256, SM_TOTAL>>>();

    dim3 qgrid(B_, C_ / 8);                      // (128, 8)
    quadv_kernel<<<qgrid, 256>>>();
    minmax_kernel<<<B_, 64>>>(out);
}

// round 13
// speedup vs baseline: 3.7130x; 1.0390x over previous
#include <cuda_runtime.h>
#include <cuda_fp16.h>
#include <cstdint>

// ===========================================================================
// Problem constants
// ===========================================================================
#define B_      128
#define RES_    25
#define D_      512
#define C_      64
#define N_      20
#define Q_      (B_ * RES_)      // 3200
#define M_ROWS  (C_ * N_)        // 1280
#define LAM     (20.0f / 512.0f)
#define ASCALE  2048.0f

// ===========================================================================
// Device scratch (allocation-free)
// ===========================================================================
__device__ float g_V[B_ * C_];            // 128 x 64 quadform sums
__device__ __half g_Ahi[M_ROWS * D_];     // G*2048 fp16 hi/lo planes (prep)
__device__ __half g_Alo[M_ROWS * D_];
__device__ __half g_Bf[Q_ * D_];          // x fp16 plane (convert)

// ===========================================================================
// PTX helpers
// ===========================================================================
__device__ __forceinline__ uint32_t smem_to_u32(const void* p) {
    uint32_t a;
    asm("{ .reg .u64 t; cvta.to.shared.u64 t, %1; cvt.u32.u64 %0, t; }"
        : "=r"(a) : "l"(p));
    return a;
}

#define CP_ASYNC16(dst_u32, src_ptr) \
    asm volatile("cp.async.cg.shared.global [%0], [%1], 16;" \
        :: "r"(dst_u32), "l"(src_ptr) : "memory")
#define CP_COMMIT() asm volatile("cp.async.commit_group;" ::: "memory")
#define CP_WAIT(n)  asm volatile("cp.async.wait_group %0;" :: "n"(n) : "memory")

__device__ __forceinline__ void ldsm_x4(uint32_t r[4], uint32_t addr) {
    asm volatile("ldmatrix.sync.aligned.m8n8.x4.shared.b16 {%0,%1,%2,%3}, [%4];"
        : "=r"(r[0]), "=r"(r[1]), "=r"(r[2]), "=r"(r[3]) : "r"(addr));
}

__device__ __forceinline__ void mma16816h(float c[4], const uint32_t a[4],
                                          uint32_t b0, uint32_t b1) {
    asm volatile(
        "mma.sync.aligned.m16n8k16.row.col.f32.f16.f16.f32 "
        "{%0,%1,%2,%3},{%4,%5,%6,%7},{%8,%9},{%0,%1,%2,%3};"
        : "+f"(c[0]), "+f"(c[1]), "+f"(c[2]), "+f"(c[3])
        : "r"(a[0]), "r"(a[1]), "r"(a[2]), "r"(a[3]), "r"(b0), "r"(b1));
}

// ===========================================================================
// Kernel 1: per-class prep (warp-coop Gram; GJ inverse; S; Cholesky; G emit)
// ===========================================================================
#define PAD_D 516

__global__ __launch_bounds__(256) void prep_kernel(const float* __restrict__ high) {
    const int c = blockIdx.x;
    const int t = threadIdx.x;
    const int lane = t & 31;
    const int wid = t >> 5;

    __shared__ float sH[N_ * PAD_D];
    __shared__ float aug[N_][2 * N_ + 1];
    __shared__ float colk[N_];
    __shared__ float sS[N_][N_ + 1];

    const float4* H4 = reinterpret_cast<const float4*>(high + (size_t)c * N_ * D_);
    for (int idx = t; idx < N_ * D_ / 4; idx += 256) {
        int r = idx >> 7;
        int k4 = idx & 127;
        *reinterpret_cast<float4*>(&sH[r * PAD_D + k4 * 4]) = H4[idx];
    }
    for (int e = t; e < N_ * N_; e += 256) {
        int i = e / N_, j = e % N_;
        aug[i][N_ + j] = (i == j) ? 1.0f : 0.0f;
    }
    __syncthreads();

    for (int p = wid; p < 210; p += 8) {
        int i = 0, rem = p;
        while (rem >= N_ - i) { rem -= N_ - i; i++; }
        int j = i + rem;
        const float* ri = sH + i * PAD_D;
        const float* rj = sH + j * PAD_D;
        float s0 = 0.f, s1 = 0.f;
        #pragma unroll
        for (int k = 0; k < 8; k++) {
            s0 = fmaf(ri[lane + k * 64],      rj[lane + k * 64],      s0);
            s1 = fmaf(ri[lane + 32 + k * 64], rj[lane + 32 + k * 64], s1);
        }
        float s = s0 + s1;
        #pragma unroll
        for (int off = 16; off > 0; off >>= 1)
            s += __shfl_xor_sync(0xffffffffu, s, off);
        if (lane == 0) {
            float v = s + (i == j ? LAM : 0.0f);
            aug[i][j] = v;
            if (i != j) aug[j][i] = v;
        }
    }
    __syncthreads();

    for (int k = 0; k < N_; k++) {
        float pinv = 1.0f / aug[k][k];
        if (t < N_) colk[t] = aug[t][k];
        __syncthreads();
        if (t < 2 * N_) aug[k][t] *= pinv;
        __syncthreads();
        for (int e = t; e < N_ * 2 * N_; e += 256) {
            int i = e / (2 * N_), j = e % (2 * N_);
            if (i != k) aug[i][j] = fmaf(-colk[i], aug[k][j], aug[i][j]);
        }
        __syncthreads();
    }

    for (int e = t; e < N_ * N_; e += 256) {
        int i = e / N_, j = e % N_;
        float acc = 0.0f;
        #pragma unroll
        for (int k = 0; k < N_; k++) acc = fmaf(aug[i][N_ + k], aug[k][N_ + j], acc);
        sS[i][j] = aug[i][N_ + j] + LAM * acc;
    }
    __syncthreads();

    for (int k = 0; k < N_; k++) {
        if (t == 0) sS[k][k] = sqrtf(sS[k][k]);
        __syncthreads();
        if (t > k && t < N_) sS[t][k] /= sS[k][k];
        __syncthreads();
        for (int e = t; e < N_ * N_; e += 256) {
            int i = e / N_, j = e % N_;
            if (j > k && i >= j) sS[i][j] = fmaf(-sS[i][k], sS[j][k], sS[i][j]);
        }
        __syncthreads();
    }

    const int kd4 = (t & 127) * 4;
    const int ihalf = t >> 7;
    __half2* Ahi2 = reinterpret_cast<__half2*>(g_Ahi + (size_t)c * N_ * D_);
    __half2* Alo2 = reinterpret_cast<__half2*>(g_Alo + (size_t)c * N_ * D_);
    #pragma unroll
    for (int r = 0; r < 10; r++) {
        const int i = ihalf + 2 * r;
        float ax = 0.f, ay = 0.f, az = 0.f, aw = 0.f;
        for (int j = i; j < N_; j++) {
            float lji = sS[j][i];
            float4 h = *reinterpret_cast<const float4*>(&sH[j * PAD_D + kd4]);
            ax = fmaf(lji, h.x, ax);
            ay = fmaf(lji, h.y, ay);
            az = fmaf(lji, h.z, az);
            aw = fmaf(lji, h.w, aw);
        }
        ax *= ASCALE; ay *= ASCALE; az *= ASCALE; aw *= ASCALE;
        __half hx = __float2half_rn(ax);
        __half hy = __float2half_rn(ay);
        __half hz = __float2half_rn(az);
        __half hw = __float2half_rn(aw);
        const int base2 = (i * D_ + kd4) >> 1;
        Ahi2[base2 + 0] = __half2(hx, hy);
        Ahi2[base2 + 1] = __half2(hz, hw);
        Alo2[base2 + 0] = __half2(
            __float2half_rn(ax - __half2float(hx)),
            __float2half_rn(ay - __half2float(hy)));
        Alo2[base2 + 1] = __half2(
            __float2half_rn(az - __half2float(hz)),
            __float2half_rn(aw - __half2float(hw)));
    }
}

// ===========================================================================
// Kernel 2: fp32 x -> fp16 plane; block 0 also zeroes g_V.
// ===========================================================================
__global__ __launch_bounds__(256) void convert_kernel(const float* __restrict__ x)
{
    if (blockIdx.x == 0) {
        for (int i = threadIdx.x; i < B_ * C_; i += 256) g_V[i] = 0.0f;
    }
    const int NB4 = Q_ * D_ / 4;
    int idx = blockIdx.x * 256 + threadIdx.x;
    const int stride = gridDim.x * 256;
    const float4* x4 = reinterpret_cast<const float4*>(x);
    __half2* b2 = reinterpret_cast<__half2*>(g_Bf);
    for (int i = idx; i < NB4; i += stride) {
        float4 v = x4[i];
        b2[i * 2 + 0] = __half2(__float2half_rn(v.x), __float2half_rn(v.y));
        b2[i * 2 + 1] = __half2(__float2half_rn(v.z), __float2half_rn(v.w));
    }
}

// ===========================================================================
// Kernel 3: HMMA fp16x2 GEMM with register-space fused V epilogue.
// Z = G_all * X^T per 128x128 tile (full K), epilogue folds z^2 into
// per-thread (rowslot x bslot) partials, warp-reduces, global atomicAdd.
// ===========================================================================
#define BM   128
#define BN   128
#define BKc  32
#define NKC  (D_ / BKc)           // 16
#define ROWB 80
#define SZ_T (128 * ROWB)
#define SA_HI 0
#define SA_LO SZ_T
#define SB_F  (2 * SZ_T)
#define STG   (3 * SZ_T)          // 30720
#define SM_TOTAL (2 * STG)        // 61440

__global__ __launch_bounds__(256) void gemm_kernel() {
    extern __shared__ char sm[];
    const uint32_t sb = smem_to_u32(sm);
    const int tid = threadIdx.x;
    const int lane = tid & 31;
    const int wid = tid >> 5;
    const int wm = wid & 3;
    const int wn = wid >> 2;
    const int m0 = blockIdx.y * BM;
    const int n0 = blockIdx.x * BN;

    float acc[2][8][4];
    #pragma unroll
    for (int i = 0; i < 2; i++)
        #pragma unroll
        for (int j = 0; j < 8; j++)
            #pragma unroll
            for (int k = 0; k < 4; k++) acc[i][j][k] = 0.0f;

    const int ar0 = tid >> 2;
    const int ac4 = (tid & 3) * 16;
    const int ak8 = (tid & 3) * 8;

    const int a_row  = wm * 32 + (lane & 15);
    const int a_kb   = ((lane >> 4) * 8) * 2;
    const uint32_t aoff = (uint32_t)(a_row * ROWB + a_kb);
    const int b_row  = wn * 64 + (lane & 7) + ((lane >> 4) * 8);
    const int b_kb   = (((lane >> 3) & 1) * 8) * 2;
    const uint32_t boff = (uint32_t)(b_row * ROWB + b_kb);

    auto load_stage = [&](int s, int kc) {
        const uint32_t base = sb + s * STG;
        const size_t kbase = (size_t)kc * BKc;
        #pragma unroll
        for (int p = 0; p < 2; p++) {
            int row = ar0 + p * 64;
            size_t ga = (size_t)(m0 + row) * D_ + kbase + ak8;
            size_t gb = (size_t)(n0 + row) * D_ + kbase + ak8;
            uint32_t soff = (uint32_t)(row * ROWB + ac4);
            CP_ASYNC16(base + SA_HI + soff, g_Ahi + ga);
            CP_ASYNC16(base + SA_LO + soff, g_Alo + ga);
            CP_ASYNC16(base + SB_F  + soff, g_Bf  + gb);
        }
    };

    load_stage(0, 0); CP_COMMIT();
    load_stage(1, 1); CP_COMMIT();

    for (int kc = 0; kc < NKC; kc++) {
        const int s = kc & 1;
        if (kc + 1 < NKC) { CP_WAIT(1); } else { CP_WAIT(0); }
        __syncthreads();

        const uint32_t base = sb + s * STG;
        #pragma unroll
        for (int ks = 0; ks < 2; ks++) {
            const uint32_t kb = ks * 32;
            uint32_t ah0[4], ah1[4], al0[4], al1[4];
            ldsm_x4(ah0, base + SA_HI + aoff + kb);
            ldsm_x4(ah1, base + SA_HI + aoff + 16 * ROWB + kb);
            ldsm_x4(al0, base + SA_LO + aoff + kb);
            ldsm_x4(al1, base + SA_LO + aoff + 16 * ROWB + kb);

            uint32_t Bf[8][2];
            #pragma unroll
            for (int g = 0; g < 4; g++) {
                uint32_t bf[4];
                ldsm_x4(bf, base + SB_F + boff + g * 16 * ROWB + kb);
                Bf[g * 2 + 0][0] = bf[0]; Bf[g * 2 + 0][1] = bf[1];
                Bf[g * 2 + 1][0] = bf[2]; Bf[g * 2 + 1][1] = bf[3];
            }

            #pragma unroll
            for (int nt = 0; nt < 8; nt++) {
                mma16816h(acc[0][nt], ah0, Bf[nt][0], Bf[nt][1]);
                mma16816h(acc[1][nt], ah1, Bf[nt][0], Bf[nt][1]);
                mma16816h(acc[0][nt], al0, Bf[nt][0], Bf[nt][1]);
                mma16816h(acc[1][nt], al1, Bf[nt][0], Bf[nt][1]);
            }
        }
        __syncthreads();

        if (kc + 2 < NKC) { load_stage(s, kc + 2); CP_COMMIT(); }
    }

    // ---- fused epilogue: fold z^2 into (rowslot, bslot) register partials ----
    const float inv = 1.0f / ASCALE;
    const int gr = lane >> 2;
    const int gc = (lane & 3) * 2;
    const int colw = n0 + wn * 64;          // warp column base (multiple of 64... n0 mult of 128)
    const int bmin = colw / RES_;
    const int roww = m0 + wm * 32;          // warp row base
    const int cmin = roww / N_;

    float pr[4][4];                          // [mt*2+hh][bslot]
    #pragma unroll
    for (int i = 0; i < 4; i++)
        #pragma unroll
        for (int j = 0; j < 4; j++) pr[i][j] = 0.0f;

    #pragma unroll
    for (int mt = 0; mt < 2; mt++) {
        #pragma unroll
        for (int nt = 0; nt < 8; nt++) {
            const int c0 = colw + nt * 8 + gc;
            const int b0i = c0 / RES_ - bmin;          // 0..3
            const int b1i = (c0 + 1) / RES_ - bmin;    // 0..3
            #pragma unroll
            for (int k = 0; k < 4; k++) {
                float z = acc[mt][nt][k] * inv;
                float z2 = z * z;
                const int bi = (k & 1) ? b1i : b0i;
                #pragma unroll
                for (int bs = 0; bs < 4; bs++)
                    pr[mt * 2 + (k >> 1)][bs] += (bi == bs) ? z2 : 0.0f;
            }
        }
    }

    // remap 4 row slots -> <=3 class groups
    float pc[3][4];
    #pragma unroll
    for (int i = 0; i < 3; i++)
        #pragma unroll
        for (int j = 0; j < 4; j++) pc[i][j] = 0.0f;
    #pragma unroll
    for (int slot = 0; slot < 4; slot++) {
        const int row = roww + (slot >> 1) * 16 + (slot & 1) * 8 + gr;
        const int ci = row / N_ - cmin;                // 0..2
        #pragma unroll
        for (int cs = 0; cs < 3; cs++)
            #pragma unroll
            for (int bs = 0; bs < 4; bs++)
                pc[cs][bs] += (ci == cs) ? pr[slot][bs] : 0.0f;
    }

    // warp-reduce the 12 cells, lane 0 commits via global atomics
    #pragma unroll
    for (int cs = 0; cs < 3; cs++) {
        #pragma unroll
        for (int bs = 0; bs < 4; bs++) {
            float v = pc[cs][bs];
            #pragma unroll
            for (int off = 16; off > 0; off >>= 1)
                v += __shfl_xor_sync(0xffffffffu, v, off);
            if (lane == 0) {
                const int c = cmin + cs;
                const int bb = bmin + bs;
                if (c < C_ && bb < B_ && v != 0.0f)
                    atomicAdd(&g_V[bb * C_ + c], v);
            }
        }
    }
}

// ===========================================================================
// Kernel 4: per-b min-max scale.
// ===========================================================================
__global__ __launch_bounds__(64) void minmax_kernel(float* __restrict__ out) {
    const int b = blockIdx.x;
    const int t = threadIdx.x;
    const int lane = t & 31;
    const int w = t >> 5;

    __shared__ float sMn[2], sMx[2];

    float v = g_V[b * C_ + t];
    float mn = v, mx = v;
    #pragma unroll
    for (int off = 16; off > 0; off >>= 1) {
        mn = fminf(mn, __shfl_xor_sync(0xffffffffu, mn, off));
        mx = fmaxf(mx, __shfl_xor_sync(0xffffffffu, mx, off));
    }
    if (lane == 0) { sMn[w] = mn; sMx[w] = mx; }
    __syncthreads();
    float gmn = fminf(sMn[0], sMn[1]);
    float gmx = fmaxf(sMx[0], sMx[1]);

    out[b * C_ + t] = (v - gmn) / (gmx - gmn);
}

// ===========================================================================
extern "C" void kernel_launch(void* const* d_in, const int* in_sizes, int n_in,
                              void* d_out, int out_size) {
    const float* x    = (const float*)d_in[0];   // (128, 25, 512)
    const float* high = (const float*)d_in[1];   // (64, 20, 512)
    float* out = (float*)d_out;                  // (128, 64)

    cudaFuncSetAttribute(gemm_kernel,
                         cudaFuncAttributeMaxDynamicSharedMemorySize, SM_TOTAL);

    convert_kernel<<<800, 256>>>(x);
    prep_kernel<<<C_, 256>>>(high);

    dim3 grid(Q_ / BN, M_ROWS / BM);             // (25, 10)
    gemm_kernel<<<grid, 256, SM_TOTAL>>>();

    minmax_kernel<<<B_, 64>>>(out);
}